// round 8
// baseline (speedup 1.0000x reference)
#include <cuda_runtime.h>
#include <cuda_bf16.h>
#include <stdint.h>

#define NNODES 8192
#define DIM    256
#define ALPHA  3.0f
#define NEG    0.2f

#define TPB  256                 // softmax threads per block (measured-best)
#define CPT  (NNODES / TPB)      // 32 columns per thread
#define VEC4 (CPT / 4)           // 8 float4 groups per thread

// Scratch (__device__ global; no cudaMalloc allowed)
__device__ float g_s2p[NNODES];  // permuted: g_s2p[idx[j]] = s2[j]

__device__ __forceinline__ float fast_tanh_alpha(float v) {
    // tanh(ALPHA*v) = 1 - 2/(exp(2*ALPHA*v)+1); exact in both saturation limits
    float e = __expf(2.0f * ALPHA * v);
    return 1.0f - 2.0f * __frcp_rn(e + 1.0f);
}

// ---------------------------------------------------------------------------
// s2 kernel: one WARP per node j (src = idx[j]); 8 dims/lane via 2x float4.
//   g_s2p[src] = tanh(a*e2[src,:]) . w[D:]
// e2 only — the s1 half is folded into the softmax kernel's prologue.
// ---------------------------------------------------------------------------
__global__ void __launch_bounds__(256)
s2_kernel(const int* __restrict__ idx,
          const float* __restrict__ e2,
          const float* __restrict__ w)
{
    const int warp = (blockIdx.x * 256 + threadIdx.x) >> 5;   // node j
    const int lane = threadIdx.x & 31;
    const int src  = idx[warp];

    const float4* r2 = (const float4*)(e2 + (size_t)src * DIM) + lane * 2;
    const float4* w2 = (const float4*)(w + DIM) + lane * 2;

    float p2 = 0.f;
    #pragma unroll
    for (int q = 0; q < 2; q++) {
        float4 b = r2[q], wb = __ldg(&w2[q]);
        p2 += fast_tanh_alpha(b.x) * wb.x + fast_tanh_alpha(b.y) * wb.y
            + fast_tanh_alpha(b.z) * wb.z + fast_tanh_alpha(b.w) * wb.w;
    }
    #pragma unroll
    for (int o = 16; o > 0; o >>= 1)
        p2 += __shfl_down_sync(0xffffffffu, p2, o);
    if (lane == 0)
        g_s2p[src] = p2;
}

// ---------------------------------------------------------------------------
// softmax: one block per row i.
// PROLOGUE (hidden under other blocks' store streams): compute
//   s1_i = tanh(a*e1[idx[i],:]) . w[:D]   -- 1 float/thread, block reduce.
// BODY (R5 measured-best): no max subtraction (logits tiny, fp32-safe),
//   vals[32] register cache -> exactly one exp/element, one block sum,
//   contiguous float4 stores. s2p (32KB) stays L1-resident.
// ---------------------------------------------------------------------------
__global__ void __launch_bounds__(TPB)
softmax_kernel(const int* __restrict__ idx,
               const float* __restrict__ e1,
               const float* __restrict__ w,
               const float* __restrict__ att_b,
               float* __restrict__ out)
{
    const int i = blockIdx.x;
    const int t = threadIdx.x;

    // ---- prologue: s1[i] dot product (256 threads x 1 element) ----
    const int src = __ldg(&idx[i]);
    float p = fast_tanh_alpha(e1[(size_t)src * DIM + t]) * __ldg(&w[t]);
    #pragma unroll
    for (int o = 16; o > 0; o >>= 1)
        p += __shfl_xor_sync(0xffffffffu, p, o);
    __shared__ float sh1[TPB / 32];
    if ((t & 31) == 0) sh1[t >> 5] = p;
    __syncthreads();
    float base = att_b[0];
    #pragma unroll
    for (int wgi = 0; wgi < TPB / 32; wgi++) base += sh1[wgi];

    // ---- body: exp(leaky(base + s2)), sum, scale, store ----
    const float4* s2p4 = (const float4*)g_s2p;

    float vals[CPT];
    float sum = 0.f;
    #pragma unroll
    for (int q = 0; q < VEC4; q++) {
        float4 s = __ldg(&s2p4[q * TPB + t]);
        #pragma unroll
        for (int u = 0; u < 4; u++) {
            float x = base + ((const float*)&s)[u];
            x = (x > 0.f) ? x : NEG * x;          // leaky_relu
            float e = __expf(x);
            vals[q * 4 + u] = e;
            sum += e;
        }
    }

    // block sum (8 warps)
    __shared__ float shs[TPB / 32];
    #pragma unroll
    for (int o = 16; o > 0; o >>= 1)
        sum += __shfl_xor_sync(0xffffffffu, sum, o);
    if ((t & 31) == 0) shs[t >> 5] = sum;
    __syncthreads();
    sum = 0.f;
    #pragma unroll
    for (int wgi = 0; wgi < TPB / 32; wgi++) sum += shs[wgi];

    const float inv = __frcp_rn(sum);

    // contiguous float4 stores (plain, cached)
    float4* row4 = (float4*)(out + (size_t)i * NNODES);
    #pragma unroll
    for (int q = 0; q < VEC4; q++) {
        float4 v;
        v.x = vals[q * 4 + 0] * inv;
        v.y = vals[q * 4 + 1] * inv;
        v.z = vals[q * 4 + 2] * inv;
        v.w = vals[q * 4 + 3] * inv;
        row4[q * TPB + t] = v;
    }
}

// ---------------------------------------------------------------------------
// Inputs: idx[int32 N], emb1_w[f32 N*D], emb2_w[f32 N*D], att_w[f32 2D],
//         att_b[f32 1].  Output: f32 N*N.
// ---------------------------------------------------------------------------
extern "C" void kernel_launch(void* const* d_in, const int* in_sizes, int n_in,
                              void* d_out, int out_size)
{
    const int*   idx  = (const int*)  d_in[0];
    const float* e1   = (const float*)d_in[1];
    const float* e2   = (const float*)d_in[2];
    const float* attw = (const float*)d_in[3];
    const float* attb = (const float*)d_in[4];
    float*       out  = (float*)d_out;

    s2_kernel<<<NNODES / 8, 256>>>(idx, e2, attw);
    softmax_kernel<<<NNODES, TPB>>>(idx, e1, attw, attb, out);
}

// round 9
// speedup vs baseline: 1.2537x; 1.2537x over previous
#include <cuda_runtime.h>
#include <cuda_bf16.h>
#include <stdint.h>

#define NNODES 8192
#define DIM    256
#define ALPHA  3.0f
#define NEG    0.2f

#define TPB  256                 // softmax threads per block (measured-best R5)
#define CPT  (NNODES / TPB)      // 32 columns per thread
#define VEC4 (CPT / 4)           // 8 float4 groups per thread

// Scratch (__device__ globals; no cudaMalloc allowed)
__device__ float g_s1[NNODES];
__device__ float g_s2p[NNODES];  // permuted: g_s2p[idx[j]] = s2[j]

// Single-op hardware tanh (sm_75+): MUFU.TANH, rel err ~2^-11 (<< 1e-3 budget)
__device__ __forceinline__ float htanh(float x) {
    float y;
    asm("tanh.approx.f32 %0, %1;" : "=f"(y) : "f"(x));
    return y;
}

// ---------------------------------------------------------------------------
// score: HALF-WARP per node (16 lanes x 16 dims each).
//   g_s1[j]    = tanh(a*e1[src,:]) . w[:D]
//   g_s2p[src] = tanh(a*e2[src,:]) . w[D:]
// Per lane: 4+4 interleaved float4 loads (each instr spans 256B contiguous,
// fully coalesced, MLP=8). tanh = 1 MUFU op. 4-step shuffle reduce.
// 128-thread blocks, 1024 blocks, no barriers, no atomics.
// ---------------------------------------------------------------------------
__global__ void __launch_bounds__(128)
score_kernel(const int* __restrict__ idx,
             const float* __restrict__ e1,
             const float* __restrict__ e2,
             const float* __restrict__ w)
{
    const int node = (blockIdx.x * 128 + threadIdx.x) >> 4;   // half-warp id
    const int sub  = threadIdx.x & 15;
    const int src  = __ldg(&idx[node]);

    const float4* r1 = (const float4*)(e1 + (size_t)src * DIM);
    const float4* r2 = (const float4*)(e2 + (size_t)src * DIM);
    const float4* w1 = (const float4*)(w);
    const float4* w2 = (const float4*)(w + DIM);

    float p1 = 0.f, p2 = 0.f;
    #pragma unroll
    for (int q = 0; q < 4; q++) {
        const int k = sub + 16 * q;                 // interleaved -> coalesced
        float4 a  = r1[k];
        float4 b  = r2[k];
        float4 wa = __ldg(&w1[k]);
        float4 wb = __ldg(&w2[k]);
        p1 += htanh(ALPHA * a.x) * wa.x + htanh(ALPHA * a.y) * wa.y
            + htanh(ALPHA * a.z) * wa.z + htanh(ALPHA * a.w) * wa.w;
        p2 += htanh(ALPHA * b.x) * wb.x + htanh(ALPHA * b.y) * wb.y
            + htanh(ALPHA * b.z) * wb.z + htanh(ALPHA * b.w) * wb.w;
    }
    // reduce within the 16-lane half-warp
    #pragma unroll
    for (int o = 8; o > 0; o >>= 1) {
        p1 += __shfl_xor_sync(0xffffffffu, p1, o);
        p2 += __shfl_xor_sync(0xffffffffu, p2, o);
    }
    if (sub == 0) {
        g_s1[node] = p1;
        g_s2p[src] = p2;
    }
}

// ---------------------------------------------------------------------------
// softmax: one block per row i — UNCHANGED from R5 (measured best, 40.5us).
// No max subtraction (logits tiny, fp32-safe). vals[32] register cache ->
// exactly one exp/element, one block sum, contiguous float4 stores.
// s2p (32KB) stays L1-resident across the rows each SM processes.
// ---------------------------------------------------------------------------
__global__ void __launch_bounds__(TPB)
softmax_kernel(const float* __restrict__ att_b,
               float* __restrict__ out)
{
    const int i = blockIdx.x;
    const int t = threadIdx.x;

    const float base = g_s1[i] + att_b[0];
    const float4* s2p4 = (const float4*)g_s2p;

    float vals[CPT];
    float sum = 0.f;
    #pragma unroll
    for (int q = 0; q < VEC4; q++) {
        float4 s = __ldg(&s2p4[q * TPB + t]);
        #pragma unroll
        for (int u = 0; u < 4; u++) {
            float x = base + ((const float*)&s)[u];
            x = (x > 0.f) ? x : NEG * x;      // leaky_relu
            float e = __expf(x);
            vals[q * 4 + u] = e;
            sum += e;
        }
    }

    // block sum (8 warps)
    __shared__ float shs[TPB / 32];
    #pragma unroll
    for (int o = 16; o > 0; o >>= 1)
        sum += __shfl_xor_sync(0xffffffffu, sum, o);
    if ((t & 31) == 0) shs[t >> 5] = sum;
    __syncthreads();
    sum = 0.f;
    #pragma unroll
    for (int wgi = 0; wgi < TPB / 32; wgi++) sum += shs[wgi];

    const float inv = __frcp_rn(sum);

    // contiguous float4 stores (plain, cached)
    float4* row4 = (float4*)(out + (size_t)i * NNODES);
    #pragma unroll
    for (int q = 0; q < VEC4; q++) {
        float4 v;
        v.x = vals[q * 4 + 0] * inv;
        v.y = vals[q * 4 + 1] * inv;
        v.z = vals[q * 4 + 2] * inv;
        v.w = vals[q * 4 + 3] * inv;
        row4[q * TPB + t] = v;
    }
}

// ---------------------------------------------------------------------------
// Inputs: idx[int32 N], emb1_w[f32 N*D], emb2_w[f32 N*D], att_w[f32 2D],
//         att_b[f32 1].  Output: f32 N*N.
// ---------------------------------------------------------------------------
extern "C" void kernel_launch(void* const* d_in, const int* in_sizes, int n_in,
                              void* d_out, int out_size)
{
    const int*   idx  = (const int*)  d_in[0];
    const float* e1   = (const float*)d_in[1];
    const float* e2   = (const float*)d_in[2];
    const float* attw = (const float*)d_in[3];
    const float* attb = (const float*)d_in[4];
    float*       out  = (float*)d_out;

    score_kernel<<<NNODES * 16 / 128, 128>>>(idx, e1, e2, attw);
    softmax_kernel<<<NNODES, TPB>>>(attb, out);
}